// round 4
// baseline (speedup 1.0000x reference)
#include <cuda_runtime.h>
#include <math.h>

#define BB   2
#define SS   2048
#define DD   1024
#define HH   16
#define HDIM 64
#define DFFN 2048
#define BH   (BB*HH)

// ---------------- scratch (static __device__, no allocations) ----------------
__device__ float g_xh [BH*SS*HDIM];
__device__ float g_q  [BH*SS*HDIM];
__device__ float g_k  [BH*SS*HDIM];
__device__ float g_kT [BH*HDIM*SS];
__device__ float g_A  [(size_t)BH*SS*SS];      // 512 MB
__device__ float g_ab [(size_t)BH*SS*128];
__device__ float g_zab[(size_t)BH*SS*128];
__device__ float g_ap [(size_t)BH*SS*128];
__device__ float g_d1 [(size_t)BH*SS*128];
__device__ float g_attnv[BH*SS*HDIM];
__device__ float g_mixed[BH*SS*HDIM];
__device__ float g_x1 [BB*SS*DD];
__device__ float g_xn2[BB*SS*DD];
__device__ float g_hb [(size_t)BB*SS*DFFN];

// ---------------- helpers ----------------
__device__ __forceinline__ unsigned long long pk2(float lo, float hi) {
    unsigned long long r;
    asm("mov.b64 %0, {%1,%2};" : "=l"(r) : "f"(lo), "f"(hi));
    return r;
}
__device__ __forceinline__ unsigned long long f2fma(unsigned long long a,
                                                    unsigned long long b,
                                                    unsigned long long c) {
    unsigned long long d;
    asm("fma.rn.f32x2 %0, %1, %2, %3;" : "=l"(d) : "l"(a), "l"(b), "l"(c));
    return d;
}
__device__ __forceinline__ float2 upk(unsigned long long v) {
    float2 f;
    asm("mov.b64 {%0,%1}, %2;" : "=f"(f.x), "=f"(f.y) : "l"(v));
    return f;
}
__device__ __forceinline__ float gelu_tanh(float x) {
    float x3 = x * x * x;
    return 0.5f * x * (1.0f + tanhf(0.7978845608028654f * (x + 0.044715f * x3)));
}
__device__ __forceinline__ float blockReduceSum(float v, float* sdata) {
    int tid = threadIdx.x;
    sdata[tid] = v; __syncthreads();
    for (int s = 128; s > 0; s >>= 1) {
        if (tid < s) sdata[tid] += sdata[tid + s];
        __syncthreads();
    }
    float r = sdata[0]; __syncthreads();
    return r;
}
__device__ __forceinline__ float blockReduceMax(float v, float* sdata) {
    int tid = threadIdx.x;
    sdata[tid] = v; __syncthreads();
    for (int s = 128; s > 0; s >>= 1) {
        if (tid < s) sdata[tid] = fmaxf(sdata[tid], sdata[tid + s]);
        __syncthreads();
    }
    float r = sdata[0]; __syncthreads();
    return r;
}

// ---------------- LayerNorm (mode 0: write head layout; mode 1: flat) ----------------
__global__ void ln_kernel(const float* __restrict__ x, const float* __restrict__ g,
                          const float* __restrict__ be, float* __restrict__ out, int mode) {
    __shared__ float sred[256];
    int row = blockIdx.x;            // 0..B*S-1
    int tid = threadIdx.x;
    const float* xr = x + (size_t)row * DD;
    float v[4];
    float s = 0.f;
#pragma unroll
    for (int kk = 0; kk < 4; kk++) { v[kk] = xr[tid + 256 * kk]; s += v[kk]; }
    s = blockReduceSum(s, sred);
    float mean = s * (1.0f / DD);
    float qv = 0.f;
#pragma unroll
    for (int kk = 0; kk < 4; kk++) { float d = v[kk] - mean; qv += d * d; }
    qv = blockReduceSum(qv, sred);
    float inv = rsqrtf(qv * (1.0f / DD) + 1e-5f);
    int b = row / SS, sidx = row % SS;
#pragma unroll
    for (int kk = 0; kk < 4; kk++) {
        int j = tid + 256 * kk;
        float y = (v[kk] - mean) * inv * g[j] + be[j];
        if (mode == 0) {
            int h = j >> 6, d = j & 63;
            out[(((size_t)(b * HH + h)) * SS + sidx) * HDIM + d] = y;
        } else {
            out[(size_t)row * DD + j] = y;
        }
    }
}

// ---------------- QKV projection; v goes into ab[:,0:64], b-half zeroed ----------------
__global__ void qkv_kernel(const float* __restrict__ xh, const float* __restrict__ Wq,
                           const float* __restrict__ Wk, const float* __restrict__ Wv,
                           float* __restrict__ qo, float* __restrict__ ko,
                           float* __restrict__ ab) {
    __shared__ float Xs[64][65];
    __shared__ float Ws[64][65];
    int s0 = blockIdx.x * 64;
    int bh = blockIdx.y;
    int h = bh % HH;
    int tid = threadIdx.x, tx = tid % 16, ty = tid / 16;
    const float* xb = xh + ((size_t)bh * SS + s0) * HDIM;
    for (int t = tid; t < 1024; t += 256) {
        int r = t / 16, c4 = t % 16;
        float4 vv = *(const float4*)(xb + r * 64 + c4 * 4);
        Xs[r][c4 * 4 + 0] = vv.x; Xs[r][c4 * 4 + 1] = vv.y;
        Xs[r][c4 * 4 + 2] = vv.z; Xs[r][c4 * 4 + 3] = vv.w;
    }
    const float* Wm[3] = { Wq + h * 4096, Wk + h * 4096, Wv + h * 4096 };
    for (int m = 0; m < 3; m++) {
        __syncthreads();
        for (int t = tid; t < 1024; t += 256) {
            int r = t / 16, c4 = t % 16;
            float4 vv = *(const float4*)(Wm[m] + r * 64 + c4 * 4);
            Ws[r][c4 * 4 + 0] = vv.x; Ws[r][c4 * 4 + 1] = vv.y;
            Ws[r][c4 * 4 + 2] = vv.z; Ws[r][c4 * 4 + 3] = vv.w;
        }
        __syncthreads();
        float acc[4][4] = {};
#pragma unroll 8
        for (int kk = 0; kk < 64; kk++) {
            float xv[4], wv[4];
#pragma unroll
            for (int i = 0; i < 4; i++) xv[i] = Xs[ty * 4 + i][kk];
#pragma unroll
            for (int j = 0; j < 4; j++) wv[j] = Ws[kk][tx * 4 + j];
#pragma unroll
            for (int i = 0; i < 4; i++)
#pragma unroll
                for (int j = 0; j < 4; j++) acc[i][j] += xv[i] * wv[j];
        }
#pragma unroll
        for (int i = 0; i < 4; i++) {
            int srow = s0 + ty * 4 + i;
            size_t base = (size_t)bh * SS + srow;
#pragma unroll
            for (int j = 0; j < 4; j++) {
                int c = tx * 4 + j;
                if (m == 0)      qo[base * HDIM + c] = acc[i][j];
                else if (m == 1) ko[base * HDIM + c] = acc[i][j];
                else { ab[base * 128 + c] = acc[i][j]; ab[base * 128 + 64 + c] = 0.f; }
            }
        }
    }
}

// ---------------- k transpose: (bh,S,64) -> (bh,64,S) ----------------
__global__ void transpose_k(const float* __restrict__ k, float* __restrict__ kT) {
    __shared__ float t[32][33];
    int s0 = blockIdx.x * 32, d0 = blockIdx.y * 32, bh = blockIdx.z;
    const float* kb = k + (size_t)bh * SS * HDIM;
    float* kTb = kT + (size_t)bh * HDIM * SS;
    for (int r = threadIdx.y; r < 32; r += 8)
        t[r][threadIdx.x] = kb[(size_t)(s0 + r) * HDIM + d0 + threadIdx.x];
    __syncthreads();
    for (int r = threadIdx.y; r < 32; r += 8)
        kTb[(size_t)(d0 + r) * SS + s0 + threadIdx.x] = t[threadIdx.x][r];
}

// ---------------- row softmax over A (rows of length S) ----------------
__global__ void softmax_kernel(float* __restrict__ A) {
    __shared__ float sred[256];
    float* ar = A + (size_t)blockIdx.x * SS;
    int tid = threadIdx.x;
    float r[8];
    float mx = -1e30f;
#pragma unroll
    for (int kk = 0; kk < 8; kk++) { r[kk] = ar[tid + 256 * kk]; mx = fmaxf(mx, r[kk]); }
    mx = blockReduceMax(mx, sred);
    float s = 0.f;
#pragma unroll
    for (int kk = 0; kk < 8; kk++) { r[kk] = __expf(r[kk] - mx); s += r[kk]; }
    s = blockReduceSum(s, sred);
    float inv = 1.0f / s;
#pragma unroll
    for (int kk = 0; kk < 8; kk++) ar[tid + 256 * kk] = r[kk] * inv;
}

// ---------------- 128x128-tile GEMM core with packed fp32x2 FMA ----------------
// C[M,N] = A[M,K](lda) * B[K,N](ldb); batch over blockIdx.z with strides.
// epi: 0 store; 1 gelu(acc+bias); 2 acc+bias+resid; 3 acc*scale
__global__ void __launch_bounds__(256, 2) gemm128(
    const float* __restrict__ A, const float* __restrict__ Bm, float* __restrict__ C,
    int M, int N, int K, int lda, int ldb, int ldc,
    size_t sA, size_t sB, size_t sC,
    int epi, const float* __restrict__ bias, const float* __restrict__ resid, float scale) {
    A  += (size_t)blockIdx.z * sA;
    Bm += (size_t)blockIdx.z * sB;
    C  += (size_t)blockIdx.z * sC;
    __shared__ float Ast[32][132];   // transposed A tile, padded
    __shared__ float Xs[32][128];
    int m0 = blockIdx.x * 128, n0 = blockIdx.y * 128;
    int tid = threadIdx.x, tx = tid % 16, ty = tid / 16;
    int r0 = ty * 8, c0 = tx * 8;
    unsigned long long acc[8][4] = {};

    for (int kt = 0; kt < K; kt += 32) {
#pragma unroll
        for (int t = 0; t < 4; t++) {
            int f = tid + t * 256;          // 0..1023
            int row = f >> 3, c4 = f & 7;   // 128 rows x 8 float4
            float4 av = *(const float4*)(A + (size_t)(m0 + row) * lda + kt + c4 * 4);
            Ast[c4 * 4 + 0][row] = av.x; Ast[c4 * 4 + 1][row] = av.y;
            Ast[c4 * 4 + 2][row] = av.z; Ast[c4 * 4 + 3][row] = av.w;
        }
#pragma unroll
        for (int t = 0; t < 4; t++) {
            int f = tid + t * 256;
            int row = f >> 5, c4 = f & 31;  // 32 rows x 32 float4
            *(float4*)(&Xs[row][c4 * 4]) =
                *(const float4*)(Bm + (size_t)(kt + row) * ldb + n0 + c4 * 4);
        }
        __syncthreads();
#pragma unroll 8
        for (int kk = 0; kk < 32; kk++) {
            float4 a0 = *(const float4*)&Ast[kk][r0];
            float4 a1 = *(const float4*)&Ast[kk][r0 + 4];
            float4 x0 = *(const float4*)&Xs[kk][c0];
            float4 x1 = *(const float4*)&Xs[kk][c0 + 4];
            unsigned long long b0 = pk2(x0.x, x0.y), b1 = pk2(x0.z, x0.w);
            unsigned long long b2 = pk2(x1.x, x1.y), b3 = pk2(x1.z, x1.w);
            float av[8] = { a0.x, a0.y, a0.z, a0.w, a1.x, a1.y, a1.z, a1.w };
#pragma unroll
            for (int i = 0; i < 8; i++) {
                unsigned long long ad = pk2(av[i], av[i]);
                acc[i][0] = f2fma(ad, b0, acc[i][0]);
                acc[i][1] = f2fma(ad, b1, acc[i][1]);
                acc[i][2] = f2fma(ad, b2, acc[i][2]);
                acc[i][3] = f2fma(ad, b3, acc[i][3]);
            }
        }
        __syncthreads();
    }
#pragma unroll
    for (int i = 0; i < 8; i++) {
        int gm = m0 + r0 + i;
        float o[8];
#pragma unroll
        for (int j2 = 0; j2 < 4; j2++) {
            float2 f = upk(acc[i][j2]);
            o[2 * j2] = f.x; o[2 * j2 + 1] = f.y;
        }
        if (epi == 1) {
#pragma unroll
            for (int jj = 0; jj < 8; jj++) o[jj] = gelu_tanh(o[jj] + bias[n0 + c0 + jj]);
        } else if (epi == 2) {
#pragma unroll
            for (int jj = 0; jj < 8; jj++)
                o[jj] = o[jj] + bias[n0 + c0 + jj] + resid[(size_t)gm * ldc + n0 + c0 + jj];
        } else if (epi == 3) {
#pragma unroll
            for (int jj = 0; jj < 8; jj++) o[jj] *= scale;
        }
        *(float4*)(C + (size_t)gm * ldc + n0 + c0)     = make_float4(o[0], o[1], o[2], o[3]);
        *(float4*)(C + (size_t)gm * ldc + n0 + c0 + 4) = make_float4(o[4], o[5], o[6], o[7]);
    }
}

// ---------------- ODE elementwise steps ----------------
#define CA 0.99500416527802576610f
#define SA 0.09983341664682815230f

__global__ void eval1_kernel(const float* __restrict__ ab, const float* __restrict__ zab,
                             const float* __restrict__ omega, float* __restrict__ d1,
                             float* __restrict__ apb, float* __restrict__ attnv, int first) {
    int i = blockIdx.x * 256 + threadIdx.x;           // < BH*SS*64
    size_t base = (size_t)(i >> 6) * 128;
    int d = i & 63;
    int bh = i >> 17;
    int h = bh & (HH - 1);
    float a  = ab[base + d],       b  = ab[base + 64 + d];
    float za = zab[base + d],      zb = zab[base + 64 + d];
    float om = omega[h * HDIM + d];
    float r2 = a * a + b * b;
    float ra = za * CA + zb * SA;
    float rb = zb * CA - za * SA;
    float da = (1.0f - r2) * a - om * b + 3.0f * (ra - a);
    float db = (1.0f - r2) * b + om * a + 3.0f * (rb - b);
    d1[base + d] = da; d1[base + 64 + d] = db;
    apb[base + d] = a + 0.02f * da;
    apb[base + 64 + d] = b + 0.02f * db;
    if (first) attnv[i] = za;     // a0 = v, b0 = 0  ->  za = A @ v = attn_v
}

__global__ void eval2_kernel(float* __restrict__ ab, const float* __restrict__ apb,
                             const float* __restrict__ zab, const float* __restrict__ d1,
                             const float* __restrict__ omega) {
    int i = blockIdx.x * 256 + threadIdx.x;
    size_t base = (size_t)(i >> 6) * 128;
    int d = i & 63;
    int bh = i >> 17;
    int h = bh & (HH - 1);
    float a   = ab[base + d],   b   = ab[base + 64 + d];
    float ap  = apb[base + d],  bp  = apb[base + 64 + d];
    float zap = zab[base + d],  zbp = zab[base + 64 + d];
    float da1 = d1[base + d],   db1 = d1[base + 64 + d];
    float om = omega[h * HDIM + d];
    float r2 = ap * ap + bp * bp;
    float ra = zap * CA + zbp * SA;
    float rb = zbp * CA - zap * SA;
    float da2 = (1.0f - r2) * ap - om * bp + 3.0f * (ra - ap);
    float db2 = (1.0f - r2) * bp + om * ap + 3.0f * (rb - bp);
    ab[base + d]      = a + 0.01f * (da1 + da2);   // 0.5*DT
    ab[base + 64 + d] = b + 0.01f * (db1 + db2);
}

__global__ void mixed_kernel(const float* __restrict__ ab, const float* __restrict__ attnv,
                             float* __restrict__ mixed) {
    int i = blockIdx.x * 256 + threadIdx.x;
    size_t base = (size_t)(i >> 6) * 128;
    int d = i & 63;
    mixed[i] = 0.3f * attnv[i] + 0.7f * ab[base + d];
}

// ---------------- output projection + residual ----------------
__global__ void proj_kernel(const float* __restrict__ mixed, const float* __restrict__ Wo,
                            const float* __restrict__ x, float* __restrict__ x1) {
    __shared__ float Xs[64][65];
    __shared__ float Ws[64][65];
    int s0 = blockIdx.x * 64;
    int bh = blockIdx.y;
    int h = bh % HH, b = bh / HH;
    int tid = threadIdx.x, tx = tid % 16, ty = tid / 16;
    const float* xb = mixed + ((size_t)bh * SS + s0) * HDIM;
    const float* Wb = Wo + h * 4096;
    for (int t = tid; t < 1024; t += 256) {
        int r = t / 16, c4 = t % 16;
        float4 vv = *(const float4*)(xb + r * 64 + c4 * 4);
        Xs[r][c4 * 4 + 0] = vv.x; Xs[r][c4 * 4 + 1] = vv.y;
        Xs[r][c4 * 4 + 2] = vv.z; Xs[r][c4 * 4 + 3] = vv.w;
        float4 wv = *(const float4*)(Wb + r * 64 + c4 * 4);
        Ws[r][c4 * 4 + 0] = wv.x; Ws[r][c4 * 4 + 1] = wv.y;
        Ws[r][c4 * 4 + 2] = wv.z; Ws[r][c4 * 4 + 3] = wv.w;
    }
    __syncthreads();
    float acc[4][4] = {};
#pragma unroll 8
    for (int kk = 0; kk < 64; kk++) {
        float xv[4], wv[4];
#pragma unroll
        for (int i = 0; i < 4; i++) xv[i] = Xs[ty * 4 + i][kk];
#pragma unroll
        for (int j = 0; j < 4; j++) wv[j] = Ws[kk][tx * 4 + j];
#pragma unroll
        for (int i = 0; i < 4; i++)
#pragma unroll
            for (int j = 0; j < 4; j++) acc[i][j] += xv[i] * wv[j];
    }
#pragma unroll
    for (int i = 0; i < 4; i++) {
        int srow = s0 + ty * 4 + i;
#pragma unroll
        for (int j = 0; j < 4; j++) {
            int c = tx * 4 + j;
            size_t o = ((size_t)b * SS + srow) * DD + h * 64 + c;
            x1[o] = x[o] + acc[i][j];
        }
    }
}

// ---------------- launch ----------------
extern "C" void kernel_launch(void* const* d_in, const int* in_sizes, int n_in,
                              void* d_out, int out_size) {
    const float* x     = (const float*)d_in[0];
    const float* Wq    = (const float*)d_in[1];
    const float* Wk    = (const float*)d_in[2];
    const float* Wv    = (const float*)d_in[3];
    const float* Wo    = (const float*)d_in[4];
    const float* omega = (const float*)d_in[5];
    const float* g1    = (const float*)d_in[6];
    const float* be1   = (const float*)d_in[7];
    const float* g2    = (const float*)d_in[8];
    const float* be2   = (const float*)d_in[9];
    const float* W1    = (const float*)d_in[10];
    const float* bf1   = (const float*)d_in[11];
    const float* W2    = (const float*)d_in[12];
    const float* bf2   = (const float*)d_in[13];
    float* out = (float*)d_out;

    float *xh, *q, *k, *kT, *A, *ab, *zab, *ap, *d1, *attnv, *mixed, *x1, *xn2, *hb;
    cudaGetSymbolAddress((void**)&xh,    g_xh);
    cudaGetSymbolAddress((void**)&q,     g_q);
    cudaGetSymbolAddress((void**)&k,     g_k);
    cudaGetSymbolAddress((void**)&kT,    g_kT);
    cudaGetSymbolAddress((void**)&A,     g_A);
    cudaGetSymbolAddress((void**)&ab,    g_ab);
    cudaGetSymbolAddress((void**)&zab,   g_zab);
    cudaGetSymbolAddress((void**)&ap,    g_ap);
    cudaGetSymbolAddress((void**)&d1,    g_d1);
    cudaGetSymbolAddress((void**)&attnv, g_attnv);
    cudaGetSymbolAddress((void**)&mixed, g_mixed);
    cudaGetSymbolAddress((void**)&x1,    g_x1);
    cudaGetSymbolAddress((void**)&xn2,   g_xn2);
    cudaGetSymbolAddress((void**)&hb,    g_hb);

    // 1) LN1 -> head layout
    ln_kernel<<<BB * SS, 256>>>(x, g1, be1, xh, 0);
    // 2) QKV (v -> ab[:,0:64], b-half zeroed)
    qkv_kernel<<<dim3(SS / 64, BH), 256>>>(xh, Wq, Wk, Wv, q, k, ab);
    // 3) k transpose for scores GEMM
    transpose_k<<<dim3(SS / 32, HDIM / 32, BH), dim3(32, 8)>>>(k, kT);
    // 4) scores = (q @ kT) * 1/8
    gemm128<<<dim3(SS / 128, SS / 128, BH), 256>>>(
        q, kT, A, SS, SS, HDIM, HDIM, SS, SS,
        (size_t)SS * HDIM, (size_t)HDIM * SS, (size_t)SS * SS,
        3, nullptr, nullptr, 0.125f);
    // 5) softmax rows
    softmax_kernel<<<BH * SS, 256>>>(A);
    // 6) 5 Heun steps (2 A-applies each, width 128)
    for (int st = 0; st < 5; st++) {
        gemm128<<<dim3(SS / 128, 1, BH), 256>>>(
            A, ab, zab, SS, 128, SS, SS, 128, 128,
            (size_t)SS * SS, (size_t)SS * 128, (size_t)SS * 128,
            0, nullptr, nullptr, 1.0f);
        eval1_kernel<<<16384, 256>>>(ab, zab, omega, d1, ap, attnv, st == 0 ? 1 : 0);
        gemm128<<<dim3(SS / 128, 1, BH), 256>>>(
            A, ap, zab, SS, 128, SS, SS, 128, 128,
            (size_t)SS * SS, (size_t)SS * 128, (size_t)SS * 128,
            0, nullptr, nullptr, 1.0f);
        eval2_kernel<<<16384, 256>>>(ab, ap, zab, d1, omega);
    }
    // 7) mix
    mixed_kernel<<<16384, 256>>>(ab, attnv, mixed);
    // 8) output projection + residual -> x1
    proj_kernel<<<dim3(SS / 64, BH), 256>>>(mixed, Wo, x, x1);
    // 9) LN2
    ln_kernel<<<BB * SS, 256>>>(x1, g2, be2, xn2, 1);
    // 10) MLP
    gemm128<<<dim3(BB * SS / 128, DFFN / 128, 1), 256>>>(
        xn2, W1, hb, BB * SS, DFFN, DD, DD, DFFN, DFFN,
        0, 0, 0, 1, bf1, nullptr, 1.0f);
    gemm128<<<dim3(BB * SS / 128, DD / 128, 1), 256>>>(
        hb, W2, out, BB * SS, DD, DFFN, DFFN, DD, DD,
        0, 0, 0, 2, bf2, x1, 1.0f);
}

// round 9
// speedup vs baseline: 1.6613x; 1.6613x over previous
#include <cuda_runtime.h>
#include <cuda_bf16.h>
#include <math.h>

#define BB   2
#define SS   2048
#define DD   1024
#define HH   16
#define HDIM 64
#define DFFN 2048
#define BH   (BB*HH)

// ---------------- scratch (static __device__, no allocations) ----------------
__device__ float g_xh [BH*SS*HDIM];
__device__ float g_q  [BH*SS*HDIM];
__device__ float g_k  [BH*SS*HDIM];
__device__ float g_kT [BH*HDIM*SS];
__device__ float g_A  [(size_t)BH*SS*SS];                 // fp32 scores (512 MB)
__device__ __nv_bfloat16 g_Ahi[(size_t)BH*SS*SS];         // softmax A hi (256 MB)
__device__ __nv_bfloat16 g_Alo[(size_t)BH*SS*SS];         // softmax A lo (256 MB)
// state in TRANSPOSED layout: [bh][n(128)][k(2048)], n<64 = a-dim, n>=64 = b-dim
__device__ float         g_st  [(size_t)BH*128*SS];
__device__ __nv_bfloat16 g_sthi[(size_t)BH*128*SS];
__device__ __nv_bfloat16 g_stlo[(size_t)BH*128*SS];
__device__ float         g_apf [(size_t)BH*128*SS];
__device__ __nv_bfloat16 g_aphi[(size_t)BH*128*SS];
__device__ __nv_bfloat16 g_aplo[(size_t)BH*128*SS];
__device__ float         g_z   [(size_t)BH*128*SS];       // A-apply output, [bh][n][k]
__device__ float         g_d1  [(size_t)BH*128*SS];
__device__ float g_attnv[(size_t)BH*64*SS];               // [bh][d][k]
__device__ float g_mixed[(size_t)BH*64*SS];               // [bh][d][k]
__device__ float g_x1 [BB*SS*DD];
__device__ float g_xn2[BB*SS*DD];
__device__ float g_hb [(size_t)BB*SS*DFFN];

// ---------------- generic helpers ----------------
__device__ __forceinline__ unsigned long long pk2(float lo, float hi) {
    unsigned long long r;
    asm("mov.b64 %0, {%1,%2};" : "=l"(r) : "f"(lo), "f"(hi));
    return r;
}
__device__ __forceinline__ unsigned long long f2fma(unsigned long long a,
                                                    unsigned long long b,
                                                    unsigned long long c) {
    unsigned long long d;
    asm("fma.rn.f32x2 %0, %1, %2, %3;" : "=l"(d) : "l"(a), "l"(b), "l"(c));
    return d;
}
__device__ __forceinline__ float2 upk(unsigned long long v) {
    float2 f;
    asm("mov.b64 {%0,%1}, %2;" : "=f"(f.x), "=f"(f.y) : "l"(v));
    return f;
}
__device__ __forceinline__ float gelu_tanh(float x) {
    float x3 = x * x * x;
    return 0.5f * x * (1.0f + tanhf(0.7978845608028654f * (x + 0.044715f * x3)));
}
__device__ __forceinline__ float blockReduceSum(float v, float* sdata) {
    int tid = threadIdx.x;
    sdata[tid] = v; __syncthreads();
    for (int s = 128; s > 0; s >>= 1) {
        if (tid < s) sdata[tid] += sdata[tid + s];
        __syncthreads();
    }
    float r = sdata[0]; __syncthreads();
    return r;
}
__device__ __forceinline__ float blockReduceMax(float v, float* sdata) {
    int tid = threadIdx.x;
    sdata[tid] = v; __syncthreads();
    for (int s = 128; s > 0; s >>= 1) {
        if (tid < s) sdata[tid] = fmaxf(sdata[tid], sdata[tid + s]);
        __syncthreads();
    }
    float r = sdata[0]; __syncthreads();
    return r;
}
__device__ __forceinline__ void split_bf16(float v, __nv_bfloat16& hi, __nv_bfloat16& lo) {
    hi = __float2bfloat16(v);
    lo = __float2bfloat16(v - __bfloat162float(hi));
}
__device__ __forceinline__ unsigned int s2u(const void* p) {
    unsigned int a;
    asm("{ .reg .u64 t; cvta.to.shared.u64 t, %1; cvt.u32.u64 %0, t; }" : "=r"(a) : "l"(p));
    return a;
}

// ---------------- warp-mma helpers (plain PTX, sm_80+: works on sm_103 target) ----------------
__device__ __forceinline__ void ldmx4(unsigned int* r, unsigned int addr) {
    asm volatile("ldmatrix.sync.aligned.m8n8.x4.shared.b16 {%0,%1,%2,%3}, [%4];"
                 : "=r"(r[0]), "=r"(r[1]), "=r"(r[2]), "=r"(r[3]) : "r"(addr));
}
__device__ __forceinline__ void mma16816(float* c, const unsigned int* a,
                                         const unsigned int b0, const unsigned int b1) {
    asm volatile(
        "mma.sync.aligned.m16n8k16.row.col.f32.bf16.bf16.f32 "
        "{%0,%1,%2,%3}, {%4,%5,%6,%7}, {%8,%9}, {%0,%1,%2,%3};"
        : "+f"(c[0]), "+f"(c[1]), "+f"(c[2]), "+f"(c[3])
        : "r"(a[0]), "r"(a[1]), "r"(a[2]), "r"(a[3]), "r"(b0), "r"(b1));
}

// ---------------- LayerNorm (mode 0: head layout; mode 1: flat) ----------------
__global__ void ln_kernel(const float* __restrict__ x, const float* __restrict__ g,
                          const float* __restrict__ be, float* __restrict__ out, int mode) {
    __shared__ float sred[256];
    int row = blockIdx.x;
    int tid = threadIdx.x;
    const float* xr = x + (size_t)row * DD;
    float v[4];
    float s = 0.f;
#pragma unroll
    for (int kk = 0; kk < 4; kk++) { v[kk] = xr[tid + 256 * kk]; s += v[kk]; }
    s = blockReduceSum(s, sred);
    float mean = s * (1.0f / DD);
    float qv = 0.f;
#pragma unroll
    for (int kk = 0; kk < 4; kk++) { float d = v[kk] - mean; qv += d * d; }
    qv = blockReduceSum(qv, sred);
    float inv = rsqrtf(qv * (1.0f / DD) + 1e-5f);
    int b = row / SS, sidx = row % SS;
#pragma unroll
    for (int kk = 0; kk < 4; kk++) {
        int j = tid + 256 * kk;
        float y = (v[kk] - mean) * inv * g[j] + be[j];
        if (mode == 0) {
            int h = j >> 6, d = j & 63;
            out[(((size_t)(b * HH + h)) * SS + sidx) * HDIM + d] = y;
        } else {
            out[(size_t)row * DD + j] = y;
        }
    }
}

// ---------------- QKV projection; v -> transposed state (a half), b half zeroed ----------------
__global__ void qkv_kernel(const float* __restrict__ xh, const float* __restrict__ Wq,
                           const float* __restrict__ Wk, const float* __restrict__ Wv,
                           float* __restrict__ qo, float* __restrict__ ko,
                           float* __restrict__ stf, __nv_bfloat16* __restrict__ sthi,
                           __nv_bfloat16* __restrict__ stlo) {
    __shared__ float Xs[64][65];
    __shared__ float Ws[64][65];
    int s0 = blockIdx.x * 64;
    int bh = blockIdx.y;
    int h = bh % HH;
    int tid = threadIdx.x, tx = tid % 16, ty = tid / 16;
    const float* xb = xh + ((size_t)bh * SS + s0) * HDIM;
    for (int t = tid; t < 1024; t += 256) {
        int r = t / 16, c4 = t % 16;
        float4 vv = *(const float4*)(xb + r * 64 + c4 * 4);
        Xs[r][c4 * 4 + 0] = vv.x; Xs[r][c4 * 4 + 1] = vv.y;
        Xs[r][c4 * 4 + 2] = vv.z; Xs[r][c4 * 4 + 3] = vv.w;
    }
    const float* Wm[3] = { Wq + h * 4096, Wk + h * 4096, Wv + h * 4096 };
    for (int m = 0; m < 3; m++) {
        __syncthreads();
        for (int t = tid; t < 1024; t += 256) {
            int r = t / 16, c4 = t % 16;
            float4 vv = *(const float4*)(Wm[m] + r * 64 + c4 * 4);
            Ws[r][c4 * 4 + 0] = vv.x; Ws[r][c4 * 4 + 1] = vv.y;
            Ws[r][c4 * 4 + 2] = vv.z; Ws[r][c4 * 4 + 3] = vv.w;
        }
        __syncthreads();
        float acc[4][4] = {};
#pragma unroll 8
        for (int kk = 0; kk < 64; kk++) {
            float xv[4], wv[4];
#pragma unroll
            for (int i = 0; i < 4; i++) xv[i] = Xs[ty * 4 + i][kk];
#pragma unroll
            for (int j = 0; j < 4; j++) wv[j] = Ws[kk][tx * 4 + j];
#pragma unroll
            for (int i = 0; i < 4; i++)
#pragma unroll
                for (int j = 0; j < 4; j++) acc[i][j] += xv[i] * wv[j];
        }
#pragma unroll
        for (int i = 0; i < 4; i++) {
            int srow = s0 + ty * 4 + i;
            size_t base = (size_t)bh * SS + srow;
#pragma unroll
            for (int j = 0; j < 4; j++) {
                int c = tx * 4 + j;
                if (m == 0)      qo[base * HDIM + c] = acc[i][j];
                else if (m == 1) ko[base * HDIM + c] = acc[i][j];
                else {
                    size_t tb = ((size_t)bh << 18) + ((size_t)c << 11) + srow; // [bh][d][s]
                    float v = acc[i][j];
                    __nv_bfloat16 hi, lo; split_bf16(v, hi, lo);
                    stf[tb] = v; sthi[tb] = hi; stlo[tb] = lo;
                    size_t tbb = tb + (64 << 11);
                    stf[tbb] = 0.f;
                    sthi[tbb] = __float2bfloat16(0.f);
                    stlo[tbb] = __float2bfloat16(0.f);
                }
            }
        }
    }
}

// ---------------- k transpose ----------------
__global__ void transpose_k(const float* __restrict__ k, float* __restrict__ kT) {
    __shared__ float t[32][33];
    int s0 = blockIdx.x * 32, d0 = blockIdx.y * 32, bh = blockIdx.z;
    const float* kb = k + (size_t)bh * SS * HDIM;
    float* kTb = kT + (size_t)bh * HDIM * SS;
    for (int r = threadIdx.y; r < 32; r += 8)
        t[r][threadIdx.x] = kb[(size_t)(s0 + r) * HDIM + d0 + threadIdx.x];
    __syncthreads();
    for (int r = threadIdx.y; r < 32; r += 8)
        kTb[(size_t)(d0 + r) * SS + s0 + threadIdx.x] = t[threadIdx.x][r];
}

// ---------------- row softmax -> bf16 hi/lo ----------------
__global__ void softmax_kernel(const float* __restrict__ A,
                               __nv_bfloat16* __restrict__ Ahi,
                               __nv_bfloat16* __restrict__ Alo) {
    __shared__ float sred[256];
    size_t rb = (size_t)blockIdx.x * SS;
    const float* ar = A + rb;
    int tid = threadIdx.x;
    float r[8];
    float mx = -1e30f;
#pragma unroll
    for (int kk = 0; kk < 8; kk++) { r[kk] = ar[tid + 256 * kk]; mx = fmaxf(mx, r[kk]); }
    mx = blockReduceMax(mx, sred);
    float s = 0.f;
#pragma unroll
    for (int kk = 0; kk < 8; kk++) { r[kk] = __expf(r[kk] - mx); s += r[kk]; }
    s = blockReduceSum(s, sred);
    float inv = 1.0f / s;
#pragma unroll
    for (int kk = 0; kk < 8; kk++) {
        float val = r[kk] * inv;
        __nv_bfloat16 hi, lo; split_bf16(val, hi, lo);
        Ahi[rb + tid + 256 * kk] = hi;
        Alo[rb + tid + 256 * kk] = lo;
    }
}

// ---------------- HMMA (mma.sync) bf16 3-split A-apply ----------------
// Z[bh][n][k=seq] = sum_t A[bh][m=seq][t] * S[bh][n][t]
// CTA: 128(m) x 128(n), 8 warps of 64x32. K chunk 64, SMEM stride 144B (conflict-free ldmatrix).
#define KC 64
#define TSTRIDE 144
#define TILE_B (128 * TSTRIDE)          // 18432
#define SMEM_HMMA (4 * TILE_B)          // 73728
__global__ void __launch_bounds__(256) apply_mma(
    const __nv_bfloat16* __restrict__ Ahi, const __nv_bfloat16* __restrict__ Alo,
    const __nv_bfloat16* __restrict__ Bhi, const __nv_bfloat16* __restrict__ Blo,
    float* __restrict__ Zt)
{
    extern __shared__ char smem[];
    unsigned int sb = s2u(smem);
    int tid = threadIdx.x, wid = tid >> 5, lane = tid & 31;
    int m0 = blockIdx.x << 7;
    int bh = blockIdx.y;
    int wm = (wid >> 2) * 64, wn = (wid & 3) * 32;

    const char* gt[4];
    gt[0] = (const char*)(Ahi + (((size_t)bh) << 22) + ((size_t)m0 << 11));
    gt[1] = (const char*)(Alo + (((size_t)bh) << 22) + ((size_t)m0 << 11));
    gt[2] = (const char*)(Bhi + (((size_t)bh) << 18));
    gt[3] = (const char*)(Blo + (((size_t)bh) << 18));

    float c[4][4][4];
#pragma unroll
    for (int i = 0; i < 4; i++)
#pragma unroll
        for (int j = 0; j < 4; j++)
#pragma unroll
            for (int r = 0; r < 4; r++) c[i][j][r] = 0.f;

    // ldmatrix lane-address components
    int arow = ((lane >> 3) & 1) * 8 + (lane & 7);
    int akad = (lane >> 4) * 8;                    // +8 k for matrices 2,3
    int brow = (lane >> 4) * 8 + (lane & 7);       // +8 n for matrices 2,3
    int bkad = ((lane >> 3) & 1) * 8;              // +8 k for matrices 1,3
    unsigned int aBase = sb + (wm + arow) * TSTRIDE + akad * 2;
    unsigned int bBase = sb + 2 * TILE_B + (wn + brow) * TSTRIDE + bkad * 2;

    for (int kt = 0; kt < SS; kt += KC) {
        // load 4 tiles: 128 rows x 64 bf16 each; 8x uint4 per row
#pragma unroll
        for (int i = 0; i < 16; i++) {
            int idx = tid + (i << 8);               // 0..4095
            int tile = idx >> 10;
            int r = (idx >> 3) & 127, c16 = idx & 7;
            *(uint4*)(smem + tile * TILE_B + r * TSTRIDE + c16 * 16) =
                *(const uint4*)(gt[tile] + (size_t)r * 4096 + (size_t)kt * 2 + (c16 << 4));
        }
        __syncthreads();
#pragma unroll
        for (int ks = 0; ks < 4; ks++) {
            unsigned int a[4][4];
            unsigned int b[2][4];
            unsigned int aOff = aBase + ks * 32;
            unsigned int bOff = bBase + ks * 32;
            // --- Ah x Bh ---
#pragma unroll
            for (int ma = 0; ma < 4; ma++) ldmx4(a[ma], aOff + ma * 16 * TSTRIDE);
#pragma unroll
            for (int p = 0; p < 2; p++) ldmx4(b[p], bOff + p * 16 * TSTRIDE);
#pragma unroll
            for (int ma = 0; ma < 4; ma++)
#pragma unroll
                for (int na = 0; na < 4; na++)
                    mma16816(c[ma][na], a[ma], b[na >> 1][(na & 1) * 2],
                             b[na >> 1][(na & 1) * 2 + 1]);
            // --- Al x Bh ---
#pragma unroll
            for (int ma = 0; ma < 4; ma++) ldmx4(a[ma], aOff + TILE_B + ma * 16 * TSTRIDE);
#pragma unroll
            for (int ma = 0; ma < 4; ma++)
#pragma unroll
                for (int na = 0; na < 4; na++)
                    mma16816(c[ma][na], a[ma], b[na >> 1][(na & 1) * 2],
                             b[na >> 1][(na & 1) * 2 + 1]);
            // --- Ah x Bl ---
#pragma unroll
            for (int ma = 0; ma < 4; ma++) ldmx4(a[ma], aOff + ma * 16 * TSTRIDE);
#pragma unroll
            for (int p = 0; p < 2; p++) ldmx4(b[p], bOff + TILE_B + p * 16 * TSTRIDE);
#pragma unroll
            for (int ma = 0; ma < 4; ma++)
#pragma unroll
                for (int na = 0; na < 4; na++)
                    mma16816(c[ma][na], a[ma], b[na >> 1][(na & 1) * 2],
                             b[na >> 1][(na & 1) * 2 + 1]);
        }
        __syncthreads();
    }

    // epilogue: c[ma][na] regs {c0:(g,2tg), c1:(g,2tg+1), c2:(g+8,2tg), c3:(g+8,2tg+1)}
    int g = lane >> 2, tg = lane & 3;
    size_t zb = (((size_t)bh) << 18) + m0;
#pragma unroll
    for (int ma = 0; ma < 4; ma++) {
        int mloc = wm + ma * 16 + g;
#pragma unroll
        for (int na = 0; na < 4; na++) {
            int nloc = wn + na * 8 + tg * 2;
            float* p = Zt + zb + ((size_t)nloc << 11) + mloc;
            p[0]          = c[ma][na][0];
            p[2048]       = c[ma][na][1];
            p[8]          = c[ma][na][2];
            p[2048 + 8]   = c[ma][na][3];
        }
    }
}

// ---------------- fp32x2 GEMM (scores + MLP) ----------------
__global__ void __launch_bounds__(256, 2) gemm128(
    const float* __restrict__ A, const float* __restrict__ Bm, float* __restrict__ C,
    int M, int N, int K, int lda, int ldb, int ldc,
    size_t sA, size_t sB, size_t sC,
    int epi, const float* __restrict__ bias, const float* __restrict__ resid, float scale) {
    A  += (size_t)blockIdx.z * sA;
    Bm += (size_t)blockIdx.z * sB;
    C  += (size_t)blockIdx.z * sC;
    __shared__ float Ast[32][132];
    __shared__ float Xs[32][128];
    int m0 = blockIdx.x * 128, n0 = blockIdx.y * 128;
    int tid = threadIdx.x, tx = tid % 16, ty = tid / 16;
    int r0 = ty * 8, c0 = tx * 8;
    unsigned long long acc[8][4] = {};

    for (int kt = 0; kt < K; kt += 32) {
#pragma unroll
        for (int t = 0; t < 4; t++) {
            int f = tid + t * 256;
            int row = f >> 3, c4 = f & 7;
            float4 av = *(const float4*)(A + (size_t)(m0 + row) * lda + kt + c4 * 4);
            Ast[c4 * 4 + 0][row] = av.x; Ast[c4 * 4 + 1][row] = av.y;
            Ast[c4 * 4 + 2][row] = av.z; Ast[c4 * 4 + 3][row] = av.w;
        }
#pragma unroll
        for (int t = 0; t < 4; t++) {
            int f = tid + t * 256;
            int row = f >> 5, c4 = f & 31;
            *(float4*)(&Xs[row][c4 * 4]) =
                *(const float4*)(Bm + (size_t)(kt + row) * ldb + n0 + c4 * 4);
        }
        __syncthreads();
#pragma unroll 8
        for (int kk = 0; kk < 32; kk++) {
            float4 a0 = *(const float4*)&Ast[kk][r0];
            float4 a1 = *(const float4*)&Ast[kk][r0 + 4];
            float4 x0 = *(const float4*)&Xs[kk][c0];
            float4 x1 = *(const float4*)&Xs[kk][c0 + 4];
            unsigned long long b0 = pk2(x0.x, x0.y), b1 = pk2(x0.z, x0.w);
            unsigned long long b2 = pk2(x1.x, x1.y), b3 = pk2(x1.z, x1.w);
            float av[8] = { a0.x, a0.y, a0.z, a0.w, a1.x, a1.y, a1.z, a1.w };
#pragma unroll
            for (int i = 0; i < 8; i++) {
                unsigned long long ad = pk2(av[i], av[i]);
                acc[i][0] = f2fma(ad, b0, acc[i][0]);
                acc[i][1] = f2fma(ad, b1, acc[i][1]);
                acc[i][2] = f2fma(ad, b2, acc[i][2]);
                acc[i][3] = f2fma(ad, b3, acc[i][3]);
            }
        }
        __syncthreads();
    }
#pragma unroll
    for (int i = 0; i < 8; i++) {
        int gm = m0 + r0 + i;
        float o[8];
#pragma unroll
        for (int j2 = 0; j2 < 4; j2++) {
            float2 f = upk(acc[i][j2]);
            o[2 * j2] = f.x; o[2 * j2 + 1] = f.y;
        }
        if (epi == 1) {
#pragma unroll
            for (int jj = 0; jj < 8; jj++) o[jj] = gelu_tanh(o[jj] + bias[n0 + c0 + jj]);
        } else if (epi == 2) {
#pragma unroll
            for (int jj = 0; jj < 8; jj++)
                o[jj] = o[jj] + bias[n0 + c0 + jj] + resid[(size_t)gm * ldc + n0 + c0 + jj];
        } else if (epi == 3) {
#pragma unroll
            for (int jj = 0; jj < 8; jj++) o[jj] *= scale;
        }
        *(float4*)(C + (size_t)gm * ldc + n0 + c0)     = make_float4(o[0], o[1], o[2], o[3]);
        *(float4*)(C + (size_t)gm * ldc + n0 + c0 + 4) = make_float4(o[4], o[5], o[6], o[7]);
    }
}

// ---------------- ODE elementwise (transposed [bh][n][k] layout) ----------------
#define CA 0.99500416527802576610f
#define SA 0.09983341664682815230f

__global__ void eval1_kernel(const float* __restrict__ st, const float* __restrict__ z,
                             const float* __restrict__ omega, float* __restrict__ d1,
                             float* __restrict__ apf, __nv_bfloat16* __restrict__ aphi,
                             __nv_bfloat16* __restrict__ aplo,
                             float* __restrict__ attnv, int first) {
    int i = blockIdx.x * 256 + threadIdx.x;   // enumerates a-elements: bh*64*2048
    int bh = i >> 17;
    int w = i & 131071;
    int d = w >> 11;
    int k = w & 2047;
    size_t base = ((size_t)bh << 18) + ((size_t)d << 11) + k;
    size_t bb = base + 131072;
    float a = st[base], b = st[bb];
    float za = z[base], zb = z[bb];
    float om = omega[((bh & (HH - 1)) << 6) + d];
    float r2 = a * a + b * b;
    float ra = za * CA + zb * SA;
    float rb = zb * CA - za * SA;
    float da = (1.0f - r2) * a - om * b + 3.0f * (ra - a);
    float db = (1.0f - r2) * b + om * a + 3.0f * (rb - b);
    d1[base] = da; d1[bb] = db;
    float apv = a + 0.02f * da, bpv = b + 0.02f * db;
    apf[base] = apv; apf[bb] = bpv;
    __nv_bfloat16 hi, lo;
    split_bf16(apv, hi, lo); aphi[base] = hi; aplo[base] = lo;
    split_bf16(bpv, hi, lo); aphi[bb] = hi; aplo[bb] = lo;
    if (first) attnv[i] = za;
}

__global__ void eval2_kernel(float* __restrict__ st, const float* __restrict__ apf,
                             const float* __restrict__ z, const float* __restrict__ d1,
                             const float* __restrict__ omega,
                             __nv_bfloat16* __restrict__ sthi, __nv_bfloat16* __restrict__ stlo) {
    int i = blockIdx.x * 256 + threadIdx.x;
    int bh = i >> 17;
    int w = i & 131071;
    int d = w >> 11;
    int k = w & 2047;
    size_t base = ((size_t)bh << 18) + ((size_t)d << 11) + k;
    size_t bb = base + 131072;
    float a = st[base], b = st[bb];
    float ap = apf[base], bp = apf[bb];
    float zap = z[base], zbp = z[bb];
    float da1 = d1[base], db1 = d1[bb];
    float om = omega[((bh & (HH - 1)) << 6) + d];
    float r2 = ap * ap + bp * bp;
    float ra = zap * CA + zbp * SA;
    float rb = zbp * CA - zap * SA;
    float da2 = (1.0f - r2) * ap - om * bp + 3.0f * (ra - ap);
    float db2 = (1.0f - r2) * bp + om * ap + 3.0f * (rb - bp);
    float na = a + 0.01f * (da1 + da2);
    float nb = b + 0.01f * (db1 + db2);
    st[base] = na; st[bb] = nb;
    __nv_bfloat16 hi, lo;
    split_bf16(na, hi, lo); sthi[base] = hi; stlo[base] = lo;
    split_bf16(nb, hi, lo); sthi[bb] = hi; stlo[bb] = lo;
}

__global__ void mixed_kernel(const float* __restrict__ st, const float* __restrict__ attnv,
                             float* __restrict__ mixed) {
    int i = blockIdx.x * 256 + threadIdx.x;
    int bh = i >> 17;
    int w = i & 131071;
    size_t base = ((size_t)bh << 18) + w;       // a-half: n = w>>11 < 64
    mixed[i] = 0.3f * attnv[i] + 0.7f * st[base];
}

// ---------------- output projection + residual (mixed in [bh][d][s]) ----------------
__global__ void proj_kernel(const float* __restrict__ mixed, const float* __restrict__ Wo,
                            const float* __restrict__ x, float* __restrict__ x1) {
    __shared__ float Xs[64][65];
    __shared__ float Ws[64][65];
    int s0 = blockIdx.x * 64;
    int bh = blockIdx.y;
    int h = bh % HH, b = bh / HH;
    int tid = threadIdx.x, tx = tid % 16, ty = tid / 16;
    const float* xb = mixed + (((size_t)bh) << 17) + s0;   // [d][s] rows stride 2048
    const float* Wb = Wo + h * 4096;
    for (int t = tid; t < 1024; t += 256) {
        int d = t >> 4, c4 = t & 15;
        float4 vv = *(const float4*)(xb + (size_t)d * 2048 + c4 * 4);
        Xs[c4 * 4 + 0][d] = vv.x; Xs[c4 * 4 + 1][d] = vv.y;
        Xs[c4 * 4 + 2][d] = vv.z; Xs[c4 * 4 + 3][d] = vv.w;
        float4 wv = *(const float4*)(Wb + (t / 16) * 64 + (t % 16) * 4);
        Ws[t / 16][(t % 16) * 4 + 0] = wv.x; Ws[t / 16][(t % 16) * 4 + 1] = wv.y;
        Ws[t / 16][(t % 16) * 4 + 2] = wv.z; Ws[t / 16][(t % 16) * 4 + 3] = wv.w;
    }
    __syncthreads();
    float acc[4][4] = {};
#pragma unroll 8
    for (int kk = 0; kk < 64; kk++) {
        float xv[4], wv[4];
#pragma unroll
        for (int i = 0; i < 4; i++) xv[i] = Xs[ty * 4 + i][kk];
#pragma unroll
        for (int j = 0; j < 4; j++) wv[j] = Ws[kk][tx * 4 + j];
#pragma unroll
        for (int i = 0; i < 4; i++)
#pragma unroll
            for (int j = 0; j < 4; j++) acc[i][j] += xv[i] * wv[j];
    }
#pragma unroll
    for (int i = 0; i < 4; i++) {
        int srow = s0 + ty * 4 + i;
#pragma unroll
        for (int j = 0; j < 4; j++) {
            int c = tx * 4 + j;
            size_t o = ((size_t)b * SS + srow) * DD + h * 64 + c;
            x1[o] = x[o] + acc[i][j];
        }
    }
}

// ---------------- launch ----------------
extern "C" void kernel_launch(void* const* d_in, const int* in_sizes, int n_in,
                              void* d_out, int out_size) {
    const float* x     = (const float*)d_in[0];
    const float* Wq    = (const float*)d_in[1];
    const float* Wk    = (const float*)d_in[2];
    const float* Wv    = (const float*)d_in[3];
    const float* Wo    = (const float*)d_in[4];
    const float* omega = (const float*)d_in[5];
    const float* g1    = (const float*)d_in[6];
    const float* be1   = (const float*)d_in[7];
    const float* g2    = (const float*)d_in[8];
    const float* be2   = (const float*)d_in[9];
    const float* W1    = (const float*)d_in[10];
    const float* bf1   = (const float*)d_in[11];
    const float* W2    = (const float*)d_in[12];
    const float* bf2   = (const float*)d_in[13];
    float* out = (float*)d_out;

    float *xh, *q, *k, *kT, *A, *st, *apf, *z, *d1, *attnv, *mixed, *x1, *xn2, *hb;
    __nv_bfloat16 *Ahi, *Alo, *sthi, *stlo, *aphi, *aplo;
    cudaGetSymbolAddress((void**)&xh,    g_xh);
    cudaGetSymbolAddress((void**)&q,     g_q);
    cudaGetSymbolAddress((void**)&k,     g_k);
    cudaGetSymbolAddress((void**)&kT,    g_kT);
    cudaGetSymbolAddress((void**)&A,     g_A);
    cudaGetSymbolAddress((void**)&Ahi,   g_Ahi);
    cudaGetSymbolAddress((void**)&Alo,   g_Alo);
    cudaGetSymbolAddress((void**)&st,    g_st);
    cudaGetSymbolAddress((void**)&sthi,  g_sthi);
    cudaGetSymbolAddress((void**)&stlo,  g_stlo);
    cudaGetSymbolAddress((void**)&apf,   g_apf);
    cudaGetSymbolAddress((void**)&aphi,  g_aphi);
    cudaGetSymbolAddress((void**)&aplo,  g_aplo);
    cudaGetSymbolAddress((void**)&z,     g_z);
    cudaGetSymbolAddress((void**)&d1,    g_d1);
    cudaGetSymbolAddress((void**)&attnv, g_attnv);
    cudaGetSymbolAddress((void**)&mixed, g_mixed);
    cudaGetSymbolAddress((void**)&x1,    g_x1);
    cudaGetSymbolAddress((void**)&xn2,   g_xn2);
    cudaGetSymbolAddress((void**)&hb,    g_hb);

    cudaFuncSetAttribute(apply_mma, cudaFuncAttributeMaxDynamicSharedMemorySize, SMEM_HMMA);

    // 1) LN1 -> head layout
    ln_kernel<<<BB * SS, 256>>>(x, g1, be1, xh, 0);
    // 2) QKV (v -> transposed state + bf16 splits)
    qkv_kernel<<<dim3(SS / 64, BH), 256>>>(xh, Wq, Wk, Wv, q, k, st, sthi, stlo);
    // 3) k transpose
    transpose_k<<<dim3(SS / 32, HDIM / 32, BH), dim3(32, 8)>>>(k, kT);
    // 4) scores = (q @ kT) * 1/8
    gemm128<<<dim3(SS / 128, SS / 128, BH), 256>>>(
        q, kT, A, SS, SS, HDIM, HDIM, SS, SS,
        (size_t)SS * HDIM, (size_t)HDIM * SS, (size_t)SS * SS,
        3, nullptr, nullptr, 0.125f);
    // 5) softmax -> bf16 hi/lo
    softmax_kernel<<<BH * SS, 256>>>(A, Ahi, Alo);
    // 6) 5 Heun steps, tensor-core (HMMA) A-applies
    for (int stp = 0; stp < 5; stp++) {
        apply_mma<<<dim3(SS / 128, BH), 256, SMEM_HMMA>>>(Ahi, Alo, sthi, stlo, z);
        eval1_kernel<<<16384, 256>>>(st, z, omega, d1, apf, aphi, aplo, attnv,
                                     stp == 0 ? 1 : 0);
        apply_mma<<<dim3(SS / 128, BH), 256, SMEM_HMMA>>>(Ahi, Alo, aphi, aplo, z);
        eval2_kernel<<<16384, 256>>>(st, apf, z, d1, omega, sthi, stlo);
    }
    // 7) mix
    mixed_kernel<<<16384, 256>>>(st, attnv, mixed);
    // 8) output projection + residual
    proj_kernel<<<dim3(SS / 64, BH), 256>>>(mixed, Wo, x, x1);
    // 9) LN2
    ln_kernel<<<BB * SS, 256>>>(x1, g2, be2, xn2, 1);
    // 10) MLP
    gemm128<<<dim3(BB * SS / 128, DFFN / 128, 1), 256>>>(
        xn2, W1, hb, BB * SS, DFFN, DD, DD, DFFN, DFFN,
        0, 0, 0, 1, bf1, nullptr, 1.0f);
    gemm128<<<dim3(BB * SS / 128, DD / 128, 1), 256>>>(
        hb, W2, out, BB * SS, DD, DFFN, DFFN, DD, DD,
        0, 0, 0, 2, bf2, x1, 1.0f);
}

// round 12
// speedup vs baseline: 2.3087x; 1.3897x over previous
#include <cuda_runtime.h>
#include <cuda_bf16.h>
#include <math.h>

#define BB   2
#define SS   2048
#define DD   1024
#define HH   16
#define HDIM 64
#define DFFN 2048
#define BH   (BB*HH)

// ---------------- scratch (static __device__, no allocations) ----------------
__device__ float g_xh [BH*SS*HDIM];
__device__ float g_q  [BH*SS*HDIM];
__device__ float g_k  [BH*SS*HDIM];
__device__ float g_kT [BH*HDIM*SS];
__device__ float g_A  [(size_t)BH*SS*SS];                 // fp32 scores (512 MB)
// A and state bf16 splits live in CHUNK-TILED + SWIZZLED layout (see aidx/sidx)
__device__ __nv_bfloat16 g_Ahi[(size_t)BH*SS*SS];
__device__ __nv_bfloat16 g_Alo[(size_t)BH*SS*SS];
__device__ float         g_st  [(size_t)BH*128*SS];       // linear [bh][n][k]
__device__ __nv_bfloat16 g_sthi[(size_t)BH*128*SS];
__device__ __nv_bfloat16 g_stlo[(size_t)BH*128*SS];
__device__ float         g_apf [(size_t)BH*128*SS];
__device__ __nv_bfloat16 g_aphi[(size_t)BH*128*SS];
__device__ __nv_bfloat16 g_aplo[(size_t)BH*128*SS];
__device__ float         g_z   [(size_t)BH*128*SS];       // apply output, [bh][n][k]
__device__ float         g_d1  [(size_t)BH*128*SS];
__device__ float g_attnv[(size_t)BH*64*SS];
__device__ float g_mixed[(size_t)BH*64*SS];
__device__ float g_x1 [BB*SS*DD];
__device__ float g_xn2[BB*SS*DD];
__device__ float g_hb [(size_t)BB*SS*DFFN];

// ---------------- tiled+swizzled index helpers ----------------
// A: [bh][k>>6][m(2048)][unit(8)^ (m&7)][elem(8)]  (each unit = 16B = 8 bf16)
__device__ __forceinline__ size_t aidx(int bh, int m, int k) {
    return ((((size_t)bh * 32 + (k >> 6)) * 2048 + m) * 8 + ((((k >> 3) & 7) ^ (m & 7)))) * 8
           + (k & 7);
}
// S: [bh][k>>6][n(128)][unit^ (n&7)][elem]
__device__ __forceinline__ size_t sidx(int bh, int n, int k) {
    return ((((size_t)bh * 32 + (k >> 6)) * 128 + n) * 8 + ((((k >> 3) & 7) ^ (n & 7)))) * 8
           + (k & 7);
}

// ---------------- generic helpers ----------------
__device__ __forceinline__ unsigned long long pk2(float lo, float hi) {
    unsigned long long r;
    asm("mov.b64 %0, {%1,%2};" : "=l"(r) : "f"(lo), "f"(hi));
    return r;
}
__device__ __forceinline__ unsigned long long f2fma(unsigned long long a,
                                                    unsigned long long b,
                                                    unsigned long long c) {
    unsigned long long d;
    asm("fma.rn.f32x2 %0, %1, %2, %3;" : "=l"(d) : "l"(a), "l"(b), "l"(c));
    return d;
}
__device__ __forceinline__ float2 upk(unsigned long long v) {
    float2 f;
    asm("mov.b64 {%0,%1}, %2;" : "=f"(f.x), "=f"(f.y) : "l"(v));
    return f;
}
__device__ __forceinline__ float gelu_tanh(float x) {
    float x3 = x * x * x;
    return 0.5f * x * (1.0f + tanhf(0.7978845608028654f * (x + 0.044715f * x3)));
}
__device__ __forceinline__ float blockReduceSum(float v, float* sdata) {
    int tid = threadIdx.x;
    sdata[tid] = v; __syncthreads();
    for (int s = 128; s > 0; s >>= 1) {
        if (tid < s) sdata[tid] += sdata[tid + s];
        __syncthreads();
    }
    float r = sdata[0]; __syncthreads();
    return r;
}
__device__ __forceinline__ float blockReduceMax(float v, float* sdata) {
    int tid = threadIdx.x;
    sdata[tid] = v; __syncthreads();
    for (int s = 128; s > 0; s >>= 1) {
        if (tid < s) sdata[tid] = fmaxf(sdata[tid], sdata[tid + s]);
        __syncthreads();
    }
    float r = sdata[0]; __syncthreads();
    return r;
}
__device__ __forceinline__ void split_bf16(float v, __nv_bfloat16& hi, __nv_bfloat16& lo) {
    hi = __float2bfloat16(v);
    lo = __float2bfloat16(v - __bfloat162float(hi));
}
__device__ __forceinline__ unsigned int s2u(const void* p) {
    unsigned int a;
    asm("{ .reg .u64 t; cvta.to.shared.u64 t, %1; cvt.u32.u64 %0, t; }" : "=r"(a) : "l"(p));
    return a;
}

// ---------------- warp-mma + async-bulk helpers (plain PTX, sm_80/90 base) ----------------
__device__ __forceinline__ void ldmx4(unsigned int* r, unsigned int addr) {
    asm volatile("ldmatrix.sync.aligned.m8n8.x4.shared.b16 {%0,%1,%2,%3}, [%4];"
                 : "=r"(r[0]), "=r"(r[1]), "=r"(r[2]), "=r"(r[3]) : "r"(addr));
}
__device__ __forceinline__ void mma16816(float* c, const unsigned int* a,
                                         const unsigned int b0, const unsigned int b1) {
    asm volatile(
        "mma.sync.aligned.m16n8k16.row.col.f32.bf16.bf16.f32 "
        "{%0,%1,%2,%3}, {%4,%5,%6,%7}, {%8,%9}, {%0,%1,%2,%3};"
        : "+f"(c[0]), "+f"(c[1]), "+f"(c[2]), "+f"(c[3])
        : "r"(a[0]), "r"(a[1]), "r"(a[2]), "r"(a[3]), "r"(b0), "r"(b1));
}
__device__ __forceinline__ void bulk_cp(unsigned int dst, const void* src,
                                        unsigned int bytes, unsigned int mbar) {
    asm volatile(
        "cp.async.bulk.shared::cta.global.mbarrier::complete_tx::bytes [%0], [%1], %2, [%3];"
        :: "r"(dst), "l"(src), "r"(bytes), "r"(mbar) : "memory");
}
__device__ __forceinline__ void mbar_init(unsigned int mbar, unsigned int cnt) {
    asm volatile("mbarrier.init.shared.b64 [%0], %1;" :: "r"(mbar), "r"(cnt) : "memory");
}
__device__ __forceinline__ void mbar_expect(unsigned int mbar, unsigned int bytes) {
    asm volatile("mbarrier.arrive.expect_tx.shared.b64 _, [%0], %1;"
                 :: "r"(mbar), "r"(bytes) : "memory");
}
__device__ __forceinline__ void mbar_wait(unsigned int mbar, unsigned int parity) {
    asm volatile(
        "{\n\t"
        ".reg .pred P1;\n\t"
        "LAB_WAIT_%=:\n\t"
        "mbarrier.try_wait.parity.acquire.cta.shared::cta.b64 P1, [%0], %1, 0x989680;\n\t"
        "@P1 bra.uni DONE_%=;\n\t"
        "bra.uni LAB_WAIT_%=;\n\t"
        "DONE_%=:\n\t"
        "}"
        :: "r"(mbar), "r"(parity) : "memory");
}

// ---------------- LayerNorm (mode 0: head layout; mode 1: flat) ----------------
__global__ void ln_kernel(const float* __restrict__ x, const float* __restrict__ g,
                          const float* __restrict__ be, float* __restrict__ out, int mode) {
    __shared__ float sred[256];
    int row = blockIdx.x;
    int tid = threadIdx.x;
    const float* xr = x + (size_t)row * DD;
    float v[4];
    float s = 0.f;
#pragma unroll
    for (int kk = 0; kk < 4; kk++) { v[kk] = xr[tid + 256 * kk]; s += v[kk]; }
    s = blockReduceSum(s, sred);
    float mean = s * (1.0f / DD);
    float qv = 0.f;
#pragma unroll
    for (int kk = 0; kk < 4; kk++) { float d = v[kk] - mean; qv += d * d; }
    qv = blockReduceSum(qv, sred);
    float inv = rsqrtf(qv * (1.0f / DD) + 1e-5f);
    int b = row / SS, sidx_ = row % SS;
#pragma unroll
    for (int kk = 0; kk < 4; kk++) {
        int j = tid + 256 * kk;
        float y = (v[kk] - mean) * inv * g[j] + be[j];
        if (mode == 0) {
            int h = j >> 6, d = j & 63;
            out[(((size_t)(b * HH + h)) * SS + sidx_) * HDIM + d] = y;
        } else {
            out[(size_t)row * DD + j] = y;
        }
    }
}

// ---------------- QKV projection; v -> state (linear fp32 + tiled bf16 splits) ----------------
__global__ void qkv_kernel(const float* __restrict__ xh, const float* __restrict__ Wq,
                           const float* __restrict__ Wk, const float* __restrict__ Wv,
                           float* __restrict__ qo, float* __restrict__ ko,
                           float* __restrict__ stf, __nv_bfloat16* __restrict__ sthi,
                           __nv_bfloat16* __restrict__ stlo) {
    __shared__ float Xs[64][65];
    __shared__ float Ws[64][65];
    int s0 = blockIdx.x * 64;
    int bh = blockIdx.y;
    int h = bh % HH;
    int tid = threadIdx.x, tx = tid % 16, ty = tid / 16;
    const float* xb = xh + ((size_t)bh * SS + s0) * HDIM;
    for (int t = tid; t < 1024; t += 256) {
        int r = t / 16, c4 = t % 16;
        float4 vv = *(const float4*)(xb + r * 64 + c4 * 4);
        Xs[r][c4 * 4 + 0] = vv.x; Xs[r][c4 * 4 + 1] = vv.y;
        Xs[r][c4 * 4 + 2] = vv.z; Xs[r][c4 * 4 + 3] = vv.w;
    }
    const float* Wm[3] = { Wq + h * 4096, Wk + h * 4096, Wv + h * 4096 };
    for (int m = 0; m < 3; m++) {
        __syncthreads();
        for (int t = tid; t < 1024; t += 256) {
            int r = t / 16, c4 = t % 16;
            float4 vv = *(const float4*)(Wm[m] + r * 64 + c4 * 4);
            Ws[r][c4 * 4 + 0] = vv.x; Ws[r][c4 * 4 + 1] = vv.y;
            Ws[r][c4 * 4 + 2] = vv.z; Ws[r][c4 * 4 + 3] = vv.w;
        }
        __syncthreads();
        float acc[4][4] = {};
#pragma unroll 8
        for (int kk = 0; kk < 64; kk++) {
            float xv[4], wv[4];
#pragma unroll
            for (int i = 0; i < 4; i++) xv[i] = Xs[ty * 4 + i][kk];
#pragma unroll
            for (int j = 0; j < 4; j++) wv[j] = Ws[kk][tx * 4 + j];
#pragma unroll
            for (int i = 0; i < 4; i++)
#pragma unroll
                for (int j = 0; j < 4; j++) acc[i][j] += xv[i] * wv[j];
        }
#pragma unroll
        for (int i = 0; i < 4; i++) {
            int srow = s0 + ty * 4 + i;
            size_t base = (size_t)bh * SS + srow;
#pragma unroll
            for (int j = 0; j < 4; j++) {
                int c = tx * 4 + j;
                if (m == 0)      qo[base * HDIM + c] = acc[i][j];
                else if (m == 1) ko[base * HDIM + c] = acc[i][j];
                else {
                    float v = acc[i][j];
                    __nv_bfloat16 hi, lo; split_bf16(v, hi, lo);
                    size_t lb = ((size_t)bh << 18) + ((size_t)c << 11) + srow;  // linear
                    stf[lb] = v; stf[lb + 131072] = 0.f;
                    size_t th = sidx(bh, c, srow), tb = sidx(bh, c + 64, srow);
                    sthi[th] = hi; stlo[th] = lo;
                    sthi[tb] = __float2bfloat16(0.f);
                    stlo[tb] = __float2bfloat16(0.f);
                }
            }
        }
    }
}

// ---------------- k transpose ----------------
__global__ void transpose_k(const float* __restrict__ k, float* __restrict__ kT) {
    __shared__ float t[32][33];
    int s0 = blockIdx.x * 32, d0 = blockIdx.y * 32, bh = blockIdx.z;
    const float* kb = k + (size_t)bh * SS * HDIM;
    float* kTb = kT + (size_t)bh * HDIM * SS;
    for (int r = threadIdx.y; r < 32; r += 8)
        t[r][threadIdx.x] = kb[(size_t)(s0 + r) * HDIM + d0 + threadIdx.x];
    __syncthreads();
    for (int r = threadIdx.y; r < 32; r += 8)
        kTb[(size_t)(d0 + r) * SS + s0 + threadIdx.x] = t[threadIdx.x][r];
}

// ---------------- row softmax -> bf16 hi/lo in tiled layout ----------------
__global__ void softmax_kernel(const float* __restrict__ A,
                               __nv_bfloat16* __restrict__ Ahi,
                               __nv_bfloat16* __restrict__ Alo) {
    __shared__ float sred[256];
    size_t rb = (size_t)blockIdx.x * SS;
    const float* ar = A + rb;
    int bh = blockIdx.x >> 11, m = blockIdx.x & 2047;
    int tid = threadIdx.x;
    float r[8];
    float mx = -1e30f;
#pragma unroll
    for (int kk = 0; kk < 8; kk++) { r[kk] = ar[tid + 256 * kk]; mx = fmaxf(mx, r[kk]); }
    mx = blockReduceMax(mx, sred);
    float s = 0.f;
#pragma unroll
    for (int kk = 0; kk < 8; kk++) { r[kk] = __expf(r[kk] - mx); s += r[kk]; }
    s = blockReduceSum(s, sred);
    float inv = 1.0f / s;
#pragma unroll
    for (int kk = 0; kk < 8; kk++) {
        float val = r[kk] * inv;
        __nv_bfloat16 hi, lo; split_bf16(val, hi, lo);
        size_t ai = aidx(bh, m, tid + 256 * kk);
        Ahi[ai] = hi;
        Alo[ai] = lo;
    }
}

// ---------------- HMMA A-apply with cp.async.bulk double-buffered pipeline ----------------
// Z[bh][n][k=seq] = sum_t A[bh][m][t] * S[bh][n][t]; CTA 128m x 128n, 8 warps 64x32.
// Tiles 16KB contiguous in gmem (chunk-tiled layout); 2 stages x 4 tiles in smem.
#define STAGE_B 65536
#define SMEM_BULK (128 + 2 * STAGE_B)   // 131200
__global__ void __launch_bounds__(256) apply_mma(
    const __nv_bfloat16* __restrict__ Ahi, const __nv_bfloat16* __restrict__ Alo,
    const __nv_bfloat16* __restrict__ Bhi, const __nv_bfloat16* __restrict__ Blo,
    float* __restrict__ Zt)
{
    extern __shared__ char smem[];
    unsigned int sb = s2u(smem);
    int tid = threadIdx.x, wid = tid >> 5, lane = tid & 31;
    int m0 = blockIdx.x << 7;
    int bh = blockIdx.y;
    int wm = (wid >> 2) * 64, wn = (wid & 3) * 32;

    unsigned int mb[2] = { sb, sb + 8 };
    if (tid == 0) { mbar_init(mb[0], 1); mbar_init(mb[1], 1); }
    __syncthreads();

    const char* pAh = (const char*)Ahi;
    const char* pAl = (const char*)Alo;
    const char* pBh = (const char*)Bhi;
    const char* pBl = (const char*)Blo;

    float c[4][4][4];
#pragma unroll
    for (int i = 0; i < 4; i++)
#pragma unroll
        for (int j = 0; j < 4; j++)
#pragma unroll
            for (int r = 0; r < 4; r++) c[i][j][r] = 0.f;

    // ldmatrix lane addressing (rows fixed per lane; swizzle XOR = lane&7)
    int arow = ((lane >> 3) & 1) * 8 + (lane & 7);
    int brow = (lane >> 4) * 8 + (lane & 7);
    int ua = (lane >> 4);          // A unit base (0/1)
    int ub = ((lane >> 3) & 1);    // B unit base (0/1)
    int rx = lane & 7;
    unsigned int aRow = (wm + arow) * 128;
    unsigned int bRow = (wn + brow) * 128;

    // prologue: issue chunk 0 into stage 0
    if (tid == 0) {
        mbar_expect(mb[0], 4 * 16384);
        unsigned int dst = sb + 128;
        size_t aoff = (((size_t)bh * 32 + 0) * 2048 + m0) * 128;
        size_t boff = (((size_t)bh * 32 + 0) * 128) * 128;
        bulk_cp(dst,          pAh + aoff, 16384, mb[0]);
        bulk_cp(dst + 16384,  pAl + aoff, 16384, mb[0]);
        bulk_cp(dst + 32768,  pBh + boff, 16384, mb[0]);
        bulk_cp(dst + 49152,  pBl + boff, 16384, mb[0]);
    }

    for (int ck = 0; ck < 32; ck++) {
        int s = ck & 1;
        if (tid == 0 && ck + 1 < 32) {
            int s2 = (ck + 1) & 1;
            mbar_expect(mb[s2], 4 * 16384);
            unsigned int dst = sb + 128 + s2 * STAGE_B;
            size_t aoff = (((size_t)bh * 32 + (ck + 1)) * 2048 + m0) * 128;
            size_t boff = (((size_t)bh * 32 + (ck + 1)) * 128) * 128;
            bulk_cp(dst,          pAh + aoff, 16384, mb[s2]);
            bulk_cp(dst + 16384,  pAl + aoff, 16384, mb[s2]);
            bulk_cp(dst + 32768,  pBh + boff, 16384, mb[s2]);
            bulk_cp(dst + 49152,  pBl + boff, 16384, mb[s2]);
        }
        mbar_wait(mb[s], (ck >> 1) & 1);

        unsigned int base = sb + 128 + s * STAGE_B;
#pragma unroll
        for (int ks = 0; ks < 4; ks++) {
            unsigned int au = (unsigned int)(((ua + 2 * ks) ^ rx) << 4);
            unsigned int bu = (unsigned int)(((ub + 2 * ks) ^ rx) << 4);
            unsigned int a[4][4];
            unsigned int b[2][4];
            // --- Ah x Bh ---
#pragma unroll
            for (int ma = 0; ma < 4; ma++) ldmx4(a[ma], base + aRow + ma * 2048 + au);
#pragma unroll
            for (int p = 0; p < 2; p++) ldmx4(b[p], base + 32768 + bRow + p * 2048 + bu);
#pragma unroll
            for (int ma = 0; ma < 4; ma++)
#pragma unroll
                for (int na = 0; na < 4; na++)
                    mma16816(c[ma][na], a[ma], b[na >> 1][(na & 1) * 2],
                             b[na >> 1][(na & 1) * 2 + 1]);
            // --- Al x Bh ---
#pragma unroll
            for (int ma = 0; ma < 4; ma++)
                ldmx4(a[ma], base + 16384 + aRow + ma * 2048 + au);
#pragma unroll
            for (int ma = 0; ma < 4; ma++)
#pragma unroll
                for (int na = 0; na < 4; na++)
                    mma16816(c[ma][na], a[ma], b[na >> 1][(na & 1) * 2],
                             b[na >> 1][(na & 1) * 2 + 1]);
            // --- Ah x Bl ---
#pragma unroll
            for (int ma = 0; ma < 4; ma++) ldmx4(a[ma], base + aRow + ma * 2048 + au);
#pragma unroll
            for (int p = 0; p < 2; p++)
                ldmx4(b[p], base + 49152 + bRow + p * 2048 + bu);
#pragma unroll
            for (int ma = 0; ma < 4; ma++)
#pragma unroll
                for (int na = 0; na < 4; na++)
                    mma16816(c[ma][na], a[ma], b[na >> 1][(na & 1) * 2],
                             b[na >> 1][(na & 1) * 2 + 1]);
        }
        __syncthreads();
    }

    // epilogue: c frags {c0:(g,2tg), c1:(g,2tg+1), c2:(g+8,2tg), c3:(g+8,2tg+1)}
    int g = lane >> 2, tg = lane & 3;
    size_t zb = (((size_t)bh) << 18) + m0;
#pragma unroll
    for (int ma = 0; ma < 4; ma++) {
        int mloc = wm + ma * 16 + g;
#pragma unroll
        for (int na = 0; na < 4; na++) {
            int nloc = wn + na * 8 + tg * 2;
            float* p = Zt + zb + ((size_t)nloc << 11) + mloc;
            p[0]          = c[ma][na][0];
            p[2048]       = c[ma][na][1];
            p[8]          = c[ma][na][2];
            p[2048 + 8]   = c[ma][na][3];
        }
    }
}

// ---------------- fp32x2 GEMM (scores + MLP) ----------------
__global__ void __launch_bounds__(256, 2) gemm128(
    const float* __restrict__ A, const float* __restrict__ Bm, float* __restrict__ C,
    int M, int N, int K, int lda, int ldb, int ldc,
    size_t sA, size_t sB, size_t sC,
    int epi, const float* __restrict__ bias, const float* __restrict__ resid, float scale) {
    A  += (size_t)blockIdx.z * sA;
    Bm += (size_t)blockIdx.z * sB;
    C  += (size_t)blockIdx.z * sC;
    __shared__ float Ast[32][132];
    __shared__ float Xs[32][128];
    int m0 = blockIdx.x * 128, n0 = blockIdx.y * 128;
    int tid = threadIdx.x, tx = tid % 16, ty = tid / 16;
    int r0 = ty * 8, c0 = tx * 8;
    unsigned long long acc[8][4] = {};

    for (int kt = 0; kt < K; kt += 32) {
#pragma unroll
        for (int t = 0; t < 4; t++) {
            int f = tid + t * 256;
            int row = f >> 3, c4 = f & 7;
            float4 av = *(const float4*)(A + (size_t)(m0 + row) * lda + kt + c4 * 4);
            Ast[c4 * 4 + 0][row] = av.x; Ast[c4 * 4 + 1][row] = av.y;
            Ast[c4 * 4 + 2][row] = av.z; Ast[c4 * 4 + 3][row] = av.w;
        }
#pragma unroll
        for (int t = 0; t < 4; t++) {
            int f = tid + t * 256;
            int row = f >> 5, c4 = f & 31;
            *(float4*)(&Xs[row][c4 * 4]) =
                *(const float4*)(Bm + (size_t)(kt + row) * ldb + n0 + c4 * 4);
        }
        __syncthreads();
#pragma unroll 8
        for (int kk = 0; kk < 32; kk++) {
            float4 a0 = *(const float4*)&Ast[kk][r0];
            float4 a1 = *(const float4*)&Ast[kk][r0 + 4];
            float4 x0 = *(const float4*)&Xs[kk][c0];
            float4 x1 = *(const float4*)&Xs[kk][c0 + 4];
            unsigned long long b0 = pk2(x0.x, x0.y), b1 = pk2(x0.z, x0.w);
            unsigned long long b2 = pk2(x1.x, x1.y), b3 = pk2(x1.z, x1.w);
            float av[8] = { a0.x, a0.y, a0.z, a0.w, a1.x, a1.y, a1.z, a1.w };
#pragma unroll
            for (int i = 0; i < 8; i++) {
                unsigned long long ad = pk2(av[i], av[i]);
                acc[i][0] = f2fma(ad, b0, acc[i][0]);
                acc[i][1] = f2fma(ad, b1, acc[i][1]);
                acc[i][2] = f2fma(ad, b2, acc[i][2]);
                acc[i][3] = f2fma(ad, b3, acc[i][3]);
            }
        }
        __syncthreads();
    }
#pragma unroll
    for (int i = 0; i < 8; i++) {
        int gm = m0 + r0 + i;
        float o[8];
#pragma unroll
        for (int j2 = 0; j2 < 4; j2++) {
            float2 f = upk(acc[i][j2]);
            o[2 * j2] = f.x; o[2 * j2 + 1] = f.y;
        }
        if (epi == 1) {
#pragma unroll
            for (int jj = 0; jj < 8; jj++) o[jj] = gelu_tanh(o[jj] + bias[n0 + c0 + jj]);
        } else if (epi == 2) {
#pragma unroll
            for (int jj = 0; jj < 8; jj++)
                o[jj] = o[jj] + bias[n0 + c0 + jj] + resid[(size_t)gm * ldc + n0 + c0 + jj];
        } else if (epi == 3) {
#pragma unroll
            for (int jj = 0; jj < 8; jj++) o[jj] *= scale;
        }
        *(float4*)(C + (size_t)gm * ldc + n0 + c0)     = make_float4(o[0], o[1], o[2], o[3]);
        *(float4*)(C + (size_t)gm * ldc + n0 + c0 + 4) = make_float4(o[4], o[5], o[6], o[7]);
    }
}

// ---------------- ODE elementwise (fp32 linear layout; bf16 splits tiled) ----------------
#define CA 0.99500416527802576610f
#define SA 0.09983341664682815230f

__global__ void eval1_kernel(const float* __restrict__ st, const float* __restrict__ z,
                             const float* __restrict__ omega, float* __restrict__ d1,
                             float* __restrict__ apf, __nv_bfloat16* __restrict__ aphi,
                             __nv_bfloat16* __restrict__ aplo,
                             float* __restrict__ attnv, int first) {
    int i = blockIdx.x * 256 + threadIdx.x;
    int bh = i >> 17;
    int w = i & 131071;
    int d = w >> 11;
    int k = w & 2047;
    size_t base = ((size_t)bh << 18) + ((size_t)d << 11) + k;
    size_t bb = base + 131072;
    float a = st[base], b = st[bb];
    float za = z[base], zb = z[bb];
    float om = omega[((bh & (HH - 1)) << 6) + d];
    float r2 = a * a + b * b;
    float ra = za * CA + zb * SA;
    float rb = zb * CA - za * SA;
    float da = (1.0f - r2) * a - om * b + 3.0f * (ra - a);
    float db = (1.0f - r2) * b + om * a + 3.0f * (rb - b);
    d1[base] = da; d1[bb] = db;
    float apv = a + 0.02f * da, bpv = b + 0.02f * db;
    apf[base] = apv; apf[bb] = bpv;
    __nv_bfloat16 hi, lo;
    size_t th = sidx(bh, d, k), tb = sidx(bh, d + 64, k);
    split_bf16(apv, hi, lo); aphi[th] = hi; aplo[th] = lo;
    split_bf16(bpv, hi, lo); aphi[tb] = hi; aplo[tb] = lo;
    if (first) attnv[i] = za;
}

__global__ void eval2_kernel(float* __restrict__ st, const float* __restrict__ apf,
                             const float* __restrict__ z, const float* __restrict__ d1,
                             const float* __restrict__ omega,
                             __nv_bfloat16* __restrict__ sthi, __nv_bfloat16* __restrict__ stlo) {
    int i = blockIdx.x * 256 + threadIdx.x;
    int bh = i >> 17;
    int w = i & 131071;
    int d = w >> 11;
    int k = w & 2047;
    size_t base = ((size_t)bh << 18) + ((size_t)d << 11) + k;
    size_t bb = base + 131072;
    float a = st[base], b = st[bb];
    float ap = apf[base], bp = apf[bb];
    float zap = z[base], zbp = z[bb];
    float da1 = d1[base], db1 = d1[bb];
    float om = omega[((bh & (HH - 1)) << 6) + d];
    float r2 = ap * ap + bp * bp;
    float ra = zap * CA + zbp * SA;
    float rb = zbp * CA - zap * SA;
    float da2 = (1.0f - r2) * ap - om * bp + 3.0f * (ra - ap);
    float db2 = (1.0f - r2) * bp + om * ap + 3.0f * (rb - bp);
    float na = a + 0.01f * (da1 + da2);
    float nb = b + 0.01f * (db1 + db2);
    st[base] = na; st[bb] = nb;
    __nv_bfloat16 hi, lo;
    size_t th = sidx(bh, d, k), tb = sidx(bh, d + 64, k);
    split_bf16(na, hi, lo); sthi[th] = hi; stlo[th] = lo;
    split_bf16(nb, hi, lo); sthi[tb] = hi; stlo[tb] = lo;
}

__global__ void mixed_kernel(const float* __restrict__ st, const float* __restrict__ attnv,
                             float* __restrict__ mixed) {
    int i = blockIdx.x * 256 + threadIdx.x;
    int bh = i >> 17;
    int w = i & 131071;
    size_t base = ((size_t)bh << 18) + w;
    mixed[i] = 0.3f * attnv[i] + 0.7f * st[base];
}

// ---------------- output projection + residual (mixed in [bh][d][s]) ----------------
__global__ void proj_kernel(const float* __restrict__ mixed, const float* __restrict__ Wo,
                            const float* __restrict__ x, float* __restrict__ x1) {
    __shared__ float Xs[64][65];
    __shared__ float Ws[64][65];
    int s0 = blockIdx.x * 64;
    int bh = blockIdx.y;
    int h = bh % HH, b = bh / HH;
    int tid = threadIdx.x, tx = tid % 16, ty = tid / 16;
    const float* xb = mixed + (((size_t)bh) << 17) + s0;
    const float* Wb = Wo + h * 4096;
    for (int t = tid; t < 1024; t += 256) {
        int d = t >> 4, c4 = t & 15;
        float4 vv = *(const float4*)(xb + (size_t)d * 2048 + c4 * 4);
        Xs[c4 * 4 + 0][d] = vv.x; Xs[c4 * 4 + 1][d] = vv.y;
        Xs[c4 * 4 + 2][d] = vv.z; Xs[c4 * 4 + 3][d] = vv.w;
        float4 wv = *(const float4*)(Wb + (t / 16) * 64 + (t % 16) * 4);
        Ws[t / 16][(t % 16) * 4 + 0] = wv.x; Ws[t / 16][(t % 16) * 4 + 1] = wv.y;
        Ws[t / 16][(t % 16) * 4 + 2] = wv.z; Ws[t / 16][(t % 16) * 4 + 3] = wv.w;
    }
    __syncthreads();
    float acc[4][4] = {};
#pragma unroll 8
    for (int kk = 0; kk < 64; kk++) {
        float xv[4], wv[4];
#pragma unroll
        for (int i = 0; i < 4; i++) xv[i] = Xs[ty * 4 + i][kk];
#pragma unroll
        for (int j = 0; j < 4; j++) wv[j] = Ws[kk][tx * 4 + j];
#pragma unroll
        for (int i = 0; i < 4; i++)
#pragma unroll
            for (int j = 0; j < 4; j++) acc[i][j] += xv[i] * wv[j];
    }
#pragma unroll
    for (int i = 0; i < 4; i++) {
        int srow = s0 + ty * 4 + i;
#pragma unroll
        for (int j = 0; j < 4; j++) {
            int c = tx * 4 + j;
            size_t o = ((size_t)b * SS + srow) * DD + h * 64 + c;
            x1[o] = x[o] + acc[i][j];
        }
    }
}

// ---------------- launch ----------------
extern "C" void kernel_launch(void* const* d_in, const int* in_sizes, int n_in,
                              void* d_out, int out_size) {
    const float* x     = (const float*)d_in[0];
    const float* Wq    = (const float*)d_in[1];
    const float* Wk    = (const float*)d_in[2];
    const float* Wv    = (const float*)d_in[3];
    const float* Wo    = (const float*)d_in[4];
    const float* omega = (const float*)d_in[5];
    const float* g1    = (const float*)d_in[6];
    const float* be1   = (const float*)d_in[7];
    const float* g2    = (const float*)d_in[8];
    const float* be2   = (const float*)d_in[9];
    const float* W1    = (const float*)d_in[10];
    const float* bf1   = (const float*)d_in[11];
    const float* W2    = (const float*)d_in[12];
    const float* bf2   = (const float*)d_in[13];
    float* out = (float*)d_out;

    float *xh, *q, *k, *kT, *A, *st, *apf, *z, *d1, *attnv, *mixed, *x1, *xn2, *hb;
    __nv_bfloat16 *Ahi, *Alo, *sthi, *stlo, *aphi, *aplo;
    cudaGetSymbolAddress((void**)&xh,    g_xh);
    cudaGetSymbolAddress((void**)&q,     g_q);
    cudaGetSymbolAddress((void**)&k,     g_k);
    cudaGetSymbolAddress((void**)&kT,    g_kT);
    cudaGetSymbolAddress((void**)&A,     g_A);
    cudaGetSymbolAddress((void**)&Ahi,   g_Ahi);
    cudaGetSymbolAddress((void**)&Alo,   g_Alo);
    cudaGetSymbolAddress((void**)&st,    g_st);
    cudaGetSymbolAddress((void**)&sthi,  g_sthi);
    cudaGetSymbolAddress((void**)&stlo,  g_stlo);
    cudaGetSymbolAddress((void**)&apf,   g_apf);
    cudaGetSymbolAddress((void**)&aphi,  g_aphi);
    cudaGetSymbolAddress((void**)&aplo,  g_aplo);
    cudaGetSymbolAddress((void**)&z,     g_z);
    cudaGetSymbolAddress((void**)&d1,    g_d1);
    cudaGetSymbolAddress((void**)&attnv, g_attnv);
    cudaGetSymbolAddress((void**)&mixed, g_mixed);
    cudaGetSymbolAddress((void**)&x1,    g_x1);
    cudaGetSymbolAddress((void**)&xn2,   g_xn2);
    cudaGetSymbolAddress((void**)&hb,    g_hb);

    cudaFuncSetAttribute(apply_mma, cudaFuncAttributeMaxDynamicSharedMemorySize, SMEM_BULK);

    // 1) LN1 -> head layout
    ln_kernel<<<BB * SS, 256>>>(x, g1, be1, xh, 0);
    // 2) QKV (v -> linear fp32 state + tiled bf16 splits)
    qkv_kernel<<<dim3(SS / 64, BH), 256>>>(xh, Wq, Wk, Wv, q, k, st, sthi, stlo);
    // 3) k transpose
    transpose_k<<<dim3(SS / 32, HDIM / 32, BH), dim3(32, 8)>>>(k, kT);
    // 4) scores = (q @ kT) * 1/8
    gemm128<<<dim3(SS / 128, SS / 128, BH), 256>>>(
        q, kT, A, SS, SS, HDIM, HDIM, SS, SS,
        (size_t)SS * HDIM, (size_t)HDIM * SS, (size_t)SS * SS,
        3, nullptr, nullptr, 0.125f);
    // 5) softmax -> tiled bf16 hi/lo
    softmax_kernel<<<BH * SS, 256>>>(A, Ahi, Alo);
    // 6) 5 Heun steps, bulk-pipelined HMMA A-applies
    for (int stp = 0; stp < 5; stp++) {
        apply_mma<<<dim3(SS / 128, BH), 256, SMEM_BULK>>>(Ahi, Alo, sthi, stlo, z);
        eval1_kernel<<<16384, 256>>>(st, z, omega, d1, apf, aphi, aplo, attnv,
                                     stp == 0 ? 1 : 0);
        apply_mma<<<dim3(SS / 128, BH), 256, SMEM_BULK>>>(Ahi, Alo, aphi, aplo, z);
        eval2_kernel<<<16384, 256>>>(st, apf, z, d1, omega, sthi, stlo);
    }
    // 7) mix
    mixed_kernel<<<16384, 256>>>(st, attnv, mixed);
    // 8) output projection + residual
    proj_kernel<<<dim3(SS / 64, BH), 256>>>(mixed, Wo, x, x1);
    // 9) LN2
    ln_kernel<<<BB * SS, 256>>>(x1, g2, be2, xn2, 1);
    // 10) MLP
    gemm128<<<dim3(BB * SS / 128, DFFN / 128, 1), 256>>>(
        xn2, W1, hb, BB * SS, DFFN, DD, DD, DFFN, DFFN,
        0, 0, 0, 1, bf1, nullptr, 1.0f);
    gemm128<<<dim3(BB * SS / 128, DD / 128, 1), 256>>>(
        hb, W2, out, BB * SS, DD, DFFN, DFFN, DD, DD,
        0, 0, 0, 2, bf2, x1, 1.0f);
}